// round 1
// baseline (speedup 1.0000x reference)
#include <cuda_runtime.h>

// out[t, v] = bias[v] + sum_{q=0..3} W[v][q] * cos(x[t])^(q+1)
// Derivation: CNOT-permuted |Ry(x)^{(x)4}> state squared, dotted with Z-signs,
// telescopes to expvals[q] = cos(x)^(q+1). Phase term cancels in |psi|^2.
//
// Layout: SEQ=2^20 elements, 40 float outputs each (160B/row). Store-BW bound.
// Block = 320 threads, processes 320 t's:
//   phase 1: thread tid computes u=cos(x[base+tid]), stores (u,u^2,u^3,u^4) to smem
//   phase 2: 10 iters; thread owns fixed v-group vv=tid%10 (coeffs in regs),
//            covers t-local = it*32 + tid/10. Warp writes 512 contiguous bytes.

#define NTHREADS 320

__global__ void __launch_bounds__(NTHREADS)
qmodel_kernel(const float* __restrict__ x,
              const float* __restrict__ W,     // (40,4) row-major
              const float* __restrict__ bias,  // (40,)
              float* __restrict__ out,         // (SEQ,40)
              int seq)
{
    __shared__ float4 su[NTHREADS];

    const int tid  = threadIdx.x;
    const long long base = (long long)blockIdx.x * NTHREADS;

    // ---- per-thread fixed coefficient vectors for v-group vv (4 outputs) ----
    const int vv = tid % 10;
    const int v0 = vv * 4;
    // rows of W for v0..v0+3 (each row is exactly one float4)
    const float4 w0 = ((const float4*)W)[v0 + 0];
    const float4 w1 = ((const float4*)W)[v0 + 1];
    const float4 w2 = ((const float4*)W)[v0 + 2];
    const float4 w3 = ((const float4*)W)[v0 + 3];
    const float4 c0 = make_float4(bias[v0], bias[v0+1], bias[v0+2], bias[v0+3]);
    const float4 c1 = make_float4(w0.x, w1.x, w2.x, w3.x);  // coeff of u
    const float4 c2 = make_float4(w0.y, w1.y, w2.y, w3.y);  // coeff of u^2
    const float4 c3 = make_float4(w0.z, w1.z, w2.z, w3.z);  // coeff of u^3
    const float4 c4 = make_float4(w0.w, w1.w, w2.w, w3.w);  // coeff of u^4

    // ---- phase 1: powers of cos(x) into smem ----
    {
        long long t = base + tid;
        if (t < seq) {
            float u  = cosf(x[t]);
            float u2 = u * u;
            su[tid] = make_float4(u, u2, u2 * u, u2 * u2);
        }
    }
    __syncthreads();

    // ---- phase 2: evaluate + store ----
    const int tt0 = tid / 10;              // 0..31
    float4* __restrict__ out4 = (float4*)out;

    #pragma unroll
    for (int it = 0; it < 10; ++it) {
        int ttl = it * 32 + tt0;           // 0..319
        long long t = base + ttl;
        if (t < seq) {
            float4 up = su[ttl];
            float4 r;
            r.x = fmaf(c4.x, up.w, fmaf(c3.x, up.z, fmaf(c2.x, up.y, fmaf(c1.x, up.x, c0.x))));
            r.y = fmaf(c4.y, up.w, fmaf(c3.y, up.z, fmaf(c2.y, up.y, fmaf(c1.y, up.x, c0.y))));
            r.z = fmaf(c4.z, up.w, fmaf(c3.z, up.z, fmaf(c2.z, up.y, fmaf(c1.z, up.x, c0.z))));
            r.w = fmaf(c4.w, up.w, fmaf(c3.w, up.z, fmaf(c2.w, up.y, fmaf(c1.w, up.x, c0.w))));
            out4[t * 10 + vv] = r;
        }
    }
}

extern "C" void kernel_launch(void* const* d_in, const int* in_sizes, int n_in,
                              void* d_out, int out_size)
{
    const float* x    = (const float*)d_in[0];
    // d_in[1] = q_weights: provably unused (global phase cancels in |psi|^2)
    const float* W    = (const float*)d_in[2];
    const float* bias = (const float*)d_in[3];
    float* out        = (float*)d_out;

    const int seq = in_sizes[0];
    const int blocks = (seq + NTHREADS - 1) / NTHREADS;
    qmodel_kernel<<<blocks, NTHREADS>>>(x, W, bias, out, seq);
}